// round 17
// baseline (speedup 1.0000x reference)
#include <cuda_runtime.h>
#include <cuda_bf16.h>

// LIF neuron scan:
//   u[t] = tau * u[t-1] + x[t];  o[t] = (u[t] > 1);  u[t] *= (1 - o[t])
// x: [B, T, N] fp32, out: [B, T, N] fp32.  B=32, T=32, N=65536.
//
// R17: R16 (LDG-16 bursts + register-free L2 prefetch of chunk 1; best,
// 83.97us / 6248 GB/s) extended with CROSS-TILE prefetch. Grid = 1024
// blocks, each handling exactly 4 column-tiles (perfect balance). Per tile,
// R16's body; additionally, after chunk-1's load burst we prefetch the NEXT
// tile's chunk 0 into L2. This covers the one remaining cold window in R16:
// block-retire -> next block's chunk-0 burst went to DRAM cold, ~9x per SM.
// Now every compute window kernel-wide is covered by an L2-warming stream,
// and chunk-0 loads of tiles 1..3 complete at L2 latency. Store runs stay
// pure back-to-back STG.128 (R9).

#define T_STEPS 32
#define B_BATCH 32
#define CHUNK   16
#define BLOCK   128
#define TILES   4

__device__ __forceinline__ void prefetch_l2(const void* p) {
    asm volatile("prefetch.global.L2 [%0];" :: "l"(p));
}

__global__ __launch_bounds__(BLOCK) void lif_scan_kernel(
    const float4* __restrict__ x,
    const float*  __restrict__ tau_p,
    float4*       __restrict__ out,
    int nv,          // N/4 (float4 lanes per (b,t) row)
    int total)       // B * nv
{
    // clamp learned decay to [0,1]
    float tau = __ldg(tau_p);
    tau = fminf(fmaxf(tau, 0.0f), 1.0f);

    const int stride = gridDim.x * BLOCK;       // columns per tile step

    int i0 = blockIdx.x * BLOCK + threadIdx.x;

#pragma unroll 1
    for (int tile = 0; tile < TILES; tile++) {
        int i = i0 + tile * stride;
        if (i >= total) break;

        int b = i / nv;          // nv is a power of two; compiler -> shift
        int j = i - b * nv;

        size_t base = (size_t)b * T_STEPS * nv + j;
        const float4* xb = x   + base;
        float4*       ob = out + base;

        const size_t half = (size_t)CHUNK * nv;

        float ux = 0.0f, uy = 0.0f, uz = 0.0f, uw = 0.0f;

        // ================= chunk 0 =================
        float4 buf[CHUNK];
#pragma unroll
        for (int t = 0; t < CHUNK; t++)
            buf[t] = __ldcs(&xb[(size_t)t * nv]);

        // register-free L2 prefetch of chunk 1 (covers compute-A window)
#pragma unroll
        for (int t = 0; t < CHUNK; t++)
            prefetch_l2(&xb[half + (size_t)t * nv]);

#pragma unroll
        for (int t = 0; t < CHUNK; t++) {
            float4 xi = buf[t];

            ux = fmaf(tau, ux, xi.x);
            uy = fmaf(tau, uy, xi.y);
            uz = fmaf(tau, uz, xi.z);
            uw = fmaf(tau, uw, xi.w);

            float4 o;
            o.x = (ux > 1.0f) ? 1.0f : 0.0f;
            o.y = (uy > 1.0f) ? 1.0f : 0.0f;
            o.z = (uz > 1.0f) ? 1.0f : 0.0f;
            o.w = (uw > 1.0f) ? 1.0f : 0.0f;

            ux = (ux > 1.0f) ? 0.0f : ux;
            uy = (uy > 1.0f) ? 0.0f : uy;
            uz = (uz > 1.0f) ? 0.0f : uz;
            uw = (uw > 1.0f) ? 0.0f : uw;

            buf[t] = o;
        }

        // store run A: 16 back-to-back streaming stores
#pragma unroll
        for (int t = 0; t < CHUNK; t++)
            __stcs(&ob[(size_t)t * nv], buf[t]);

        // ================= chunk 1 =================
#pragma unroll
        for (int t = 0; t < CHUNK; t++)
            buf[t] = __ldcs(&xb[half + (size_t)t * nv]);

        // cross-tile prefetch: next tile's chunk 0 (covers compute-B window)
        if (tile + 1 < TILES) {
            int inext = i0 + (tile + 1) * stride;
            if (inext < total) {
                int bn = inext / nv;
                int jn = inext - bn * nv;
                const float4* xn = x + (size_t)bn * T_STEPS * nv + jn;
#pragma unroll
                for (int t = 0; t < CHUNK; t++)
                    prefetch_l2(&xn[(size_t)t * nv]);
            }
        }

#pragma unroll
        for (int t = 0; t < CHUNK; t++) {
            float4 xi = buf[t];

            ux = fmaf(tau, ux, xi.x);
            uy = fmaf(tau, uy, xi.y);
            uz = fmaf(tau, uz, xi.z);
            uw = fmaf(tau, uw, xi.w);

            float4 o;
            o.x = (ux > 1.0f) ? 1.0f : 0.0f;
            o.y = (uy > 1.0f) ? 1.0f : 0.0f;
            o.z = (uz > 1.0f) ? 1.0f : 0.0f;
            o.w = (uw > 1.0f) ? 1.0f : 0.0f;

            ux = (ux > 1.0f) ? 0.0f : ux;
            uy = (uy > 1.0f) ? 0.0f : uy;
            uz = (uz > 1.0f) ? 0.0f : uz;
            uw = (uw > 1.0f) ? 0.0f : uw;

            buf[t] = o;
        }

        // store run B: 16 back-to-back streaming stores
#pragma unroll
        for (int t = 0; t < CHUNK; t++)
            __stcs(&ob[half + (size_t)t * nv], buf[t]);
    }
}

extern "C" void kernel_launch(void* const* d_in, const int* in_sizes, int n_in,
                              void* d_out, int out_size)
{
    const float* x   = (const float*)d_in[0];   // [B, T, N] fp32
    const float* tau = (const float*)d_in[1];   // [1] fp32

    int total_elems = in_sizes[0];                       // B*T*N
    int N  = total_elems / (B_BATCH * T_STEPS);
    int nv = N / 4;                                      // float4 per (b,t) row
    int total_threads = B_BATCH * nv;                    // B * nv

    // each block covers TILES tiles of BLOCK columns
    int grid = (total_threads + BLOCK * TILES - 1) / (BLOCK * TILES);

    lif_scan_kernel<<<grid, BLOCK>>>(
        (const float4*)x, tau, (float4*)d_out, nv, total_threads);
}